// round 10
// baseline (speedup 1.0000x reference)
#include <cuda_runtime.h>
#include <cuda_fp16.h>
#include <cstdint>

#define N_REFLNS 2000000
#define N_IMAGES 8192
#define N_RAC    1000000
#define MC       8
#define D_META   16
#define HIDDEN   32
#define LOG_2PI_F 1.8378770664093453f

#define REFL_BLOCKS 444   // 3 blocks/SM * 148 SMs, persistent

// ---------------- scratch (static device globals; no allocation) ----------------
__device__ float4 g_zT[N_RAC * 2];       // z transposed: (N_RAC, 8)
__device__ float  g_img_sum[N_IMAGES];
__device__ float  g_img_cnt[N_IMAGES];
__device__ float  g_kl_sum;
__device__ unsigned g_done;

// ---------------- helpers ----------------
__device__ __forceinline__ void split_pair(float x, float y, unsigned& hi, unsigned& lo) {
    __half2 h = __floats2half2_rn(x, y);
    float2 hf = __half22float2(h);
    __half2 l = __floats2half2_rn(x - hf.x, y - hf.y);
    hi = *reinterpret_cast<unsigned*>(&h);
    lo = *reinterpret_cast<unsigned*>(&l);
}

__device__ __forceinline__ void mma16(float4& d,
                                      unsigned a0, unsigned a1, unsigned a2, unsigned a3,
                                      unsigned b0, unsigned b1) {
    asm("mma.sync.aligned.m16n8k16.row.col.f32.f16.f16.f32 "
        "{%0,%1,%2,%3}, {%4,%5,%6,%7}, {%8,%9}, {%0,%1,%2,%3};"
        : "+f"(d.x), "+f"(d.y), "+f"(d.z), "+f"(d.w)
        : "r"(a0), "r"(a1), "r"(a2), "r"(a3), "r"(b0), "r"(b1));
}

__device__ __forceinline__ float softplus_f(float x) {
    float ax = fabsf(x);
    float t  = __expf(-ax);
    float l  = (t > 0.0078125f) ? __logf(1.0f + t) : fmaf(-0.5f * t, t, t);
    return fmaxf(x, 0.0f) + l;
}

// ---------------- kernel 1: init + z transpose + KL ----------------
__global__ __launch_bounds__(256) void zkl_kernel(const float* __restrict__ q_loc,
                                                  const float* __restrict__ q_ls,
                                                  const float* __restrict__ eps) {
    int m = blockIdx.x * 256 + threadIdx.x;
    if (m < N_IMAGES) { g_img_sum[m] = 0.0f; g_img_cnt[m] = 0.0f; }
    if (m == 0) { g_kl_sum = 0.0f; g_done = 0u; }
    float kl = 0.0f;
    if (m < N_RAC) {
        float loc = q_loc[m];
        float ls  = q_ls[m];
        float s   = __expf(ls);
        kl = fmaf(0.5f, fmaf(s, s, fmaf(loc, loc, -1.0f)), -ls);
        float z[8];
#pragma unroll
        for (int c = 0; c < 8; c++)
            z[c] = fmaf(s, __ldcs(eps + (size_t)c * N_RAC + m), loc);
        g_zT[2 * m]     = make_float4(z[0], z[1], z[2], z[3]);
        g_zT[2 * m + 1] = make_float4(z[4], z[5], z[6], z[7]);
    }
#pragma unroll
    for (int off = 16; off; off >>= 1)
        kl += __shfl_down_sync(0xffffffffu, kl, off);
    __shared__ float wsum[8];
    int lane = threadIdx.x & 31, wid = threadIdx.x >> 5;
    if (lane == 0) wsum[wid] = kl;
    __syncthreads();
    if (threadIdx.x == 0) {
        float t = 0.0f;
#pragma unroll
        for (int i = 0; i < 8; i++) t += wsum[i];
        atomicAdd(&g_kl_sum, t);
    }
}

// segmented warp reduce + atomic; lanes with img<0 carry v=0
// (popc(mask) counts reflections per image — do NOT pre-merge lanes; R7 lesson)
__device__ __forceinline__ void seg_atomic(float v, int img, int lane) {
    unsigned mask = __match_any_sync(0xffffffffu, img);
    int hi = 31 - __clz(mask);
#pragma unroll
    for (int off = 1; off < 32; off <<= 1) {
        float o = __shfl_down_sync(0xffffffffu, v, off);
        if (lane + off <= hi) v += o;
    }
    if (img >= 0 && lane == (__ffs(mask) - 1)) {
        atomicAdd(&g_img_sum[img], v);
        atomicAdd(&g_img_cnt[img], (float)__popc(mask));
    }
}

// per-chunk register buffer
struct ChunkBuf {
    float2 va[2][4];
    int    mid[4];
    float  io[4];
    float  sg[4];
    int    img[4];
};

__device__ __forceinline__ void load_chunk(ChunkBuf& b, int base, int q, int tig,
                                           const float* __restrict__ metadata,
                                           const float* __restrict__ iobs,
                                           const float* __restrict__ sigiobs,
                                           const int* __restrict__ image_id,
                                           const int* __restrict__ miller_id) {
    int r[4] = {base + q, base + q + 8, base + 16 + q, base + 24 + q};
#pragma unroll
    for (int t = 0; t < 2; t++) {
        const float* Ma = metadata + (size_t)r[2 * t] * D_META;
        const float* Mb = metadata + (size_t)r[2 * t + 1] * D_META;
        b.va[t][0] = __ldcs((const float2*)(Ma + 2 * tig));
        b.va[t][1] = __ldcs((const float2*)(Mb + 2 * tig));
        b.va[t][2] = __ldcs((const float2*)(Ma + 2 * tig + 8));
        b.va[t][3] = __ldcs((const float2*)(Mb + 2 * tig + 8));
    }
#pragma unroll
    for (int i = 0; i < 4; i++) b.mid[i] = __ldcs(miller_id + r[i]);
#pragma unroll
    for (int i = 0; i < 4; i++) { b.io[i] = __ldcs(iobs + r[i]); b.sg[i] = __ldcs(sigiobs + r[i]); }
#pragma unroll
    for (int i = 0; i < 4; i++) b.img[i] = __ldcs(image_id + r[i]);
}

// ---------------- kernel 2: pipelined fp16x3 tensor MLP + likelihood ------------
__global__ __launch_bounds__(128, 3) void refl_kernel(const float* __restrict__ metadata,
                                                      const float* __restrict__ W1,
                                                      const float* __restrict__ b1,
                                                      const float* __restrict__ W2,
                                                      const float* __restrict__ b2,
                                                      const float* __restrict__ iobs,
                                                      const float* __restrict__ sigiobs,
                                                      const int*   __restrict__ image_id,
                                                      const int*   __restrict__ miller_id,
                                                      float*       __restrict__ out) {
    int tid  = threadIdx.x;
    int w    = tid >> 5;
    int lane = tid & 31;
    int q    = lane >> 2;
    int tig  = lane & 3;

    // ---- weight fragments (hi/lo fp16), loaded once per warp ----
    unsigned w1h[4][2], w1l[4][2];
#pragma unroll
    for (int j = 0; j < 4; j++) {
        int col = 8 * j + q;
        split_pair(W1[(2 * tig) * HIDDEN + col],     W1[(2 * tig + 1) * HIDDEN + col], w1h[j][0], w1l[j][0]);
        split_pair(W1[(2 * tig + 8) * HIDDEN + col], W1[(2 * tig + 9) * HIDDEN + col], w1h[j][1], w1l[j][1]);
    }
    unsigned w2h[2][2], w2l[2][2];
#pragma unroll
    for (int s = 0; s < 2; s++) {
        int k0 = 16 * s + 2 * tig;
        split_pair(W2[k0 * MC + q],       W2[(k0 + 1) * MC + q], w2h[s][0], w2l[s][0]);
        split_pair(W2[(k0 + 8) * MC + q], W2[(k0 + 9) * MC + q], w2h[s][1], w2l[s][1]);
    }
    float b1x[4], b1y[4];
#pragma unroll
    for (int j = 0; j < 4; j++) { b1x[j] = b1[8 * j + 2 * tig]; b1y[j] = b1[8 * j + 2 * tig + 1]; }
    float b2x = b2[2 * tig], b2y = b2[2 * tig + 1];

    const float* zTf = (const float*)g_zT;
    const int nchunks = N_REFLNS / 32;     // 62500 exact
    int gwarp  = blockIdx.x * 4 + w;
    int nwarps = gridDim.x * 4;

    // ---- pipeline prologue: prefetch first chunk ----
    ChunkBuf nxt;
    if (gwarp < nchunks)
        load_chunk(nxt, gwarp * 32, q, tig, metadata, iobs, sigiobs, image_id, miller_id);

    for (int chunk = gwarp; chunk < nchunks; chunk += nwarps) {
        ChunkBuf cur = nxt;                 // register copy; loads arrived last iter
        int base = chunk * 32;
        int r[4] = {base + q, base + q + 8, base + 16 + q, base + 24 + q};

        // zT gather for CURRENT chunk (mid already resident) — overlaps the MLP
        float2 fv[4];
#pragma unroll
        for (int i = 0; i < 4; i++)
            fv[i] = *(const float2*)(zTf + (size_t)cur.mid[i] * 8 + 2 * tig);

        // prefetch NEXT chunk — in flight during this chunk's compute
        int nc = chunk + nwarps;
        if (nc < nchunks)
            load_chunk(nxt, nc * 32, q, tig, metadata, iobs, sigiobs, image_id, miller_id);

        // ---- compute both subtiles ----
        float llv[4]; int imgv[4];
#pragma unroll
        for (int t = 0; t < 2; t++) {
            unsigned ah[4], al[4];
            split_pair(cur.va[t][0].x, cur.va[t][0].y, ah[0], al[0]);
            split_pair(cur.va[t][1].x, cur.va[t][1].y, ah[1], al[1]);
            split_pair(cur.va[t][2].x, cur.va[t][2].y, ah[2], al[2]);
            split_pair(cur.va[t][3].x, cur.va[t][3].y, ah[3], al[3]);

            float4 acc[4];
#pragma unroll
            for (int j = 0; j < 4; j++) {
                acc[j] = make_float4(b1x[j], b1y[j], b1x[j], b1y[j]);
                mma16(acc[j], ah[0], ah[1], ah[2], ah[3], w1h[j][0], w1h[j][1]);
                mma16(acc[j], al[0], al[1], al[2], al[3], w1h[j][0], w1h[j][1]);
                mma16(acc[j], ah[0], ah[1], ah[2], ah[3], w1l[j][0], w1l[j][1]);
            }

            float4 p = make_float4(b2x, b2y, b2x, b2y);
#pragma unroll
            for (int s = 0; s < 2; s++) {
                const float4& cA = acc[2 * s];
                const float4& cB = acc[2 * s + 1];
                unsigned a2h[4], a2l[4];
                split_pair(fmaxf(cA.x, 0.0f), fmaxf(cA.y, 0.0f), a2h[0], a2l[0]);
                split_pair(fmaxf(cA.z, 0.0f), fmaxf(cA.w, 0.0f), a2h[1], a2l[1]);
                split_pair(fmaxf(cB.x, 0.0f), fmaxf(cB.y, 0.0f), a2h[2], a2l[2]);
                split_pair(fmaxf(cB.z, 0.0f), fmaxf(cB.w, 0.0f), a2h[3], a2l[3]);
                mma16(p, a2h[0], a2h[1], a2h[2], a2h[3], w2h[s][0], w2h[s][1]);
                mma16(p, a2l[0], a2l[1], a2l[2], a2l[3], w2h[s][0], w2h[s][1]);
                mma16(p, a2h[0], a2h[1], a2h[2], a2h[3], w2l[s][0], w2l[s][1]);
            }

            int iq = 2 * t, iq8 = 2 * t + 1;
            float s0 = softplus_f(p.x), s1 = softplus_f(p.y);
            float s2 = softplus_f(p.z), s3 = softplus_f(p.w);

            float invq  = 1.0f / cur.sg[iq];
            float invq8 = 1.0f / cur.sg[iq8];

            float ip0 = fv[iq].x  * fv[iq].x  * s0, ip1 = fv[iq].y  * fv[iq].y  * s1;
            float ip2 = fv[iq8].x * fv[iq8].x * s2, ip3 = fv[iq8].y * fv[iq8].y * s3;
            float siq  = ip0 + ip1;
            float siq8 = ip2 + ip3;
            float r0q  = (ip0 - cur.io[iq])  * invq,  r1q  = (ip1 - cur.io[iq])  * invq;
            float r0q8 = (ip2 - cur.io[iq8]) * invq8, r1q8 = (ip3 - cur.io[iq8]) * invq8;
            float ssq  = fmaf(r0q,  r0q,  r1q  * r1q);
            float ssq8 = fmaf(r0q8, r0q8, r1q8 * r1q8);

#pragma unroll
            for (int off = 1; off < 4; off <<= 1) {
                siq  += __shfl_xor_sync(0xffffffffu, siq,  off);
                ssq  += __shfl_xor_sync(0xffffffffu, ssq,  off);
                siq8 += __shfl_xor_sync(0xffffffffu, siq8, off);
                ssq8 += __shfl_xor_sync(0xffffffffu, ssq8, off);
            }

            llv[iq] = 0.0f; llv[iq8] = 0.0f;
            imgv[iq] = -1;  imgv[iq8] = -1;
            if (tig == 0) {
                __stcs(out + r[iq],  siq  * 0.125f);
                __stcs(out + r[iq8], siq8 * 0.125f);
                llv[iq]  = fmaf(-0.5f, ssq,  -8.0f * (__logf(cur.sg[iq])  + 0.5f * LOG_2PI_F));
                llv[iq8] = fmaf(-0.5f, ssq8, -8.0f * (__logf(cur.sg[iq8]) + 0.5f * LOG_2PI_F));
                imgv[iq]  = cur.img[iq];
                imgv[iq8] = cur.img[iq8];
            }
        }

        seg_atomic(llv[0], imgv[0], lane);
        seg_atomic(llv[1], imgv[1], lane);
        seg_atomic(llv[2], imgv[2], lane);
        seg_atomic(llv[3], imgv[3], lane);
    }

    // ---- fused finalize: last block to finish reduces images + writes scalars --
    __shared__ unsigned s_last;
    __syncthreads();
    if (tid == 0) {
        __threadfence();
        unsigned t = atomicAdd(&g_done, 1u);
        s_last = (t == gridDim.x - 1) ? 1u : 0u;
    }
    __syncthreads();
    if (s_last) {
        float acc = 0.0f;
        for (int i = tid; i < N_IMAGES; i += 128)
            acc += g_img_sum[i] * (1.0f / fmaxf(g_img_cnt[i], 1.0f));
#pragma unroll
        for (int off = 16; off; off >>= 1)
            acc += __shfl_down_sync(0xffffffffu, acc, off);
        __shared__ float wsum[4];
        if (lane == 0) wsum[w] = acc;
        __syncthreads();
        if (tid == 0) {
            float total = wsum[0] + wsum[1] + wsum[2] + wsum[3];
            out[N_REFLNS]     = -(total / (float)MC) / (float)N_IMAGES;
            out[N_REFLNS + 1] = g_kl_sum * (1.0f / (float)N_RAC);
        }
    }
}

// ---------------- launch ----------------
extern "C" void kernel_launch(void* const* d_in, const int* in_sizes, int n_in,
                              void* d_out, int out_size) {
    const float* q_loc     = (const float*)d_in[0];
    const float* q_ls      = (const float*)d_in[1];
    const float* eps       = (const float*)d_in[2];
    const float* metadata  = (const float*)d_in[3];
    const float* W1        = (const float*)d_in[4];
    const float* b1        = (const float*)d_in[5];
    const float* W2        = (const float*)d_in[6];
    const float* b2        = (const float*)d_in[7];
    const float* iobs      = (const float*)d_in[8];
    const float* sigiobs   = (const float*)d_in[9];
    const int*   image_id  = (const int*)d_in[10];
    const int*   miller_id = (const int*)d_in[11];
    float* out = (float*)d_out;

    zkl_kernel<<<(N_RAC + 255) / 256, 256>>>(q_loc, q_ls, eps);
    refl_kernel<<<REFL_BLOCKS, 128>>>(metadata, W1, b1, W2, b2,
                                      iobs, sigiobs, image_id, miller_id, out);
}

// round 11
// speedup vs baseline: 1.0856x; 1.0856x over previous
#include <cuda_runtime.h>
#include <cuda_fp16.h>
#include <cstdint>

#define N_REFLNS 2000000
#define N_IMAGES 8192
#define N_RAC    1000000
#define MC       8
#define D_META   16
#define HIDDEN   32
#define LOG_2PI_F 1.8378770664093453f

// ---------------- scratch (static device globals; no allocation) ----------------
__device__ float4 g_zT[N_RAC * 2];       // z transposed: (N_RAC, 8)
__device__ float  g_img_sum[N_IMAGES];
__device__ float  g_img_cnt[N_IMAGES];
__device__ float  g_kl_sum;
__device__ unsigned g_done;

// ---------------- helpers ----------------
__device__ __forceinline__ void split_pair(float x, float y, unsigned& hi, unsigned& lo) {
    __half2 h = __floats2half2_rn(x, y);
    float2 hf = __half22float2(h);
    __half2 l = __floats2half2_rn(x - hf.x, y - hf.y);
    hi = *reinterpret_cast<unsigned*>(&h);
    lo = *reinterpret_cast<unsigned*>(&l);
}

__device__ __forceinline__ void mma16(float4& d,
                                      unsigned a0, unsigned a1, unsigned a2, unsigned a3,
                                      unsigned b0, unsigned b1) {
    asm("mma.sync.aligned.m16n8k16.row.col.f32.f16.f16.f32 "
        "{%0,%1,%2,%3}, {%4,%5,%6,%7}, {%8,%9}, {%0,%1,%2,%3};"
        : "+f"(d.x), "+f"(d.y), "+f"(d.z), "+f"(d.w)
        : "r"(a0), "r"(a1), "r"(a2), "r"(a3), "r"(b0), "r"(b1));
}

__device__ __forceinline__ float softplus_f(float x) {
    float ax = fabsf(x);
    float t  = __expf(-ax);
    float l  = (t > 0.0078125f) ? __logf(1.0f + t) : fmaf(-0.5f * t, t, t);
    return fmaxf(x, 0.0f) + l;
}

// ---------------- kernel 1: init + z transpose + KL ----------------
__global__ __launch_bounds__(256) void zkl_kernel(const float* __restrict__ q_loc,
                                                  const float* __restrict__ q_ls,
                                                  const float* __restrict__ eps) {
    int m = blockIdx.x * 256 + threadIdx.x;
    if (m < N_IMAGES) { g_img_sum[m] = 0.0f; g_img_cnt[m] = 0.0f; }
    if (m == 0) { g_kl_sum = 0.0f; g_done = 0u; }
    float kl = 0.0f;
    if (m < N_RAC) {
        float loc = q_loc[m];
        float ls  = q_ls[m];
        float s   = __expf(ls);
        kl = fmaf(0.5f, fmaf(s, s, fmaf(loc, loc, -1.0f)), -ls);
        float z[8];
#pragma unroll
        for (int c = 0; c < 8; c++)
            z[c] = fmaf(s, __ldcs(eps + (size_t)c * N_RAC + m), loc);
        g_zT[2 * m]     = make_float4(z[0], z[1], z[2], z[3]);
        g_zT[2 * m + 1] = make_float4(z[4], z[5], z[6], z[7]);
    }
#pragma unroll
    for (int off = 16; off; off >>= 1)
        kl += __shfl_down_sync(0xffffffffu, kl, off);
    __shared__ float wsum[8];
    int lane = threadIdx.x & 31, wid = threadIdx.x >> 5;
    if (lane == 0) wsum[wid] = kl;
    __syncthreads();
    if (threadIdx.x == 0) {
        float t = 0.0f;
#pragma unroll
        for (int i = 0; i < 8; i++) t += wsum[i];
        atomicAdd(&g_kl_sum, t);
    }
}

// segmented warp reduce + atomic; lanes with img<0 carry v=0
// (popc(mask) counts reflections per image — do NOT pre-merge lanes; R7 lesson)
__device__ __forceinline__ void seg_atomic(float v, int img, int lane) {
    unsigned mask = __match_any_sync(0xffffffffu, img);
    int hi = 31 - __clz(mask);
#pragma unroll
    for (int off = 1; off < 32; off <<= 1) {
        float o = __shfl_down_sync(0xffffffffu, v, off);
        if (lane + off <= hi) v += o;
    }
    if (img >= 0 && lane == (__ffs(mask) - 1)) {
        atomicAdd(&g_img_sum[img], v);
        atomicAdd(&g_img_cnt[img], (float)__popc(mask));
    }
}

// ---------------- kernel 2: fp16x3 tensor MLP + likelihood (R8 structure) -------
// Load-hoisted, NOT software-pipelined: 4 blocks/SM occupancy is the better
// latency hider (R9 lesson: pipelining cost regs 147 / occ 18% and regressed).
__global__ __launch_bounds__(128, 4) void refl_kernel(const float* __restrict__ metadata,
                                                      const float* __restrict__ W1,
                                                      const float* __restrict__ b1,
                                                      const float* __restrict__ W2,
                                                      const float* __restrict__ b2,
                                                      const float* __restrict__ iobs,
                                                      const float* __restrict__ sigiobs,
                                                      const int*   __restrict__ image_id,
                                                      const int*   __restrict__ miller_id,
                                                      float*       __restrict__ out) {
    int tid  = threadIdx.x;
    int w    = tid >> 5;
    int lane = tid & 31;
    int q    = lane >> 2;   // groupID: row within m16
    int tig  = lane & 3;    // thread-in-group: k/col pair selector

    // ---- weight fragments (hi/lo fp16), loaded once per warp ----
    unsigned w1h[4][2], w1l[4][2];
#pragma unroll
    for (int j = 0; j < 4; j++) {
        int col = 8 * j + q;
        split_pair(W1[(2 * tig) * HIDDEN + col],     W1[(2 * tig + 1) * HIDDEN + col], w1h[j][0], w1l[j][0]);
        split_pair(W1[(2 * tig + 8) * HIDDEN + col], W1[(2 * tig + 9) * HIDDEN + col], w1h[j][1], w1l[j][1]);
    }
    unsigned w2h[2][2], w2l[2][2];
#pragma unroll
    for (int s = 0; s < 2; s++) {
        int k0 = 16 * s + 2 * tig;
        split_pair(W2[k0 * MC + q],       W2[(k0 + 1) * MC + q], w2h[s][0], w2l[s][0]);
        split_pair(W2[(k0 + 8) * MC + q], W2[(k0 + 9) * MC + q], w2h[s][1], w2l[s][1]);
    }
    float b1x[4], b1y[4];
#pragma unroll
    for (int j = 0; j < 4; j++) { b1x[j] = b1[8 * j + 2 * tig]; b1y[j] = b1[8 * j + 2 * tig + 1]; }
    float b2x = b2[2 * tig], b2y = b2[2 * tig + 1];

    const float* zTf = (const float*)g_zT;
    const int nchunks = N_REFLNS / 32;     // 62500 exact
    int gwarp  = blockIdx.x * 4 + w;
    int nwarps = gridDim.x * 4;

    for (int chunk = gwarp; chunk < nchunks; chunk += nwarps) {
        int base = chunk * 32;
        int r[4] = {base + q, base + q + 8, base + 16 + q, base + 24 + q};

        // ======== PHASE 1: issue ALL independent loads back-to-back ========
        float2 va[2][4];
#pragma unroll
        for (int t = 0; t < 2; t++) {
            const float* Ma = metadata + (size_t)r[2 * t] * D_META;
            const float* Mb = metadata + (size_t)r[2 * t + 1] * D_META;
            va[t][0] = __ldcs((const float2*)(Ma + 2 * tig));
            va[t][1] = __ldcs((const float2*)(Mb + 2 * tig));
            va[t][2] = __ldcs((const float2*)(Ma + 2 * tig + 8));
            va[t][3] = __ldcs((const float2*)(Mb + 2 * tig + 8));
        }
        int   mid[4], img[4];
        float io[4], sg[4];
#pragma unroll
        for (int i = 0; i < 4; i++) mid[i] = __ldcs(miller_id + r[i]);
#pragma unroll
        for (int i = 0; i < 4; i++) { io[i] = __ldcs(iobs + r[i]); sg[i] = __ldcs(sigiobs + r[i]); }
#pragma unroll
        for (int i = 0; i < 4; i++) img[i] = __ldcs(image_id + r[i]);
        // zT gather issued BEFORE the MLP — overlaps all MMA work
        float2 fv[4];
#pragma unroll
        for (int i = 0; i < 4; i++)
            fv[i] = *(const float2*)(zTf + (size_t)mid[i] * 8 + 2 * tig);

        // ======== PHASE 2: compute both subtiles ========
        float llv[4]; int imgv[4];
#pragma unroll
        for (int t = 0; t < 2; t++) {
            unsigned ah[4], al[4];
            split_pair(va[t][0].x, va[t][0].y, ah[0], al[0]);
            split_pair(va[t][1].x, va[t][1].y, ah[1], al[1]);
            split_pair(va[t][2].x, va[t][2].y, ah[2], al[2]);
            split_pair(va[t][3].x, va[t][3].y, ah[3], al[3]);

            // layer1: h = meta @ W1 + b1 (bias in C init), 3-term fp16
            float4 acc[4];
#pragma unroll
            for (int j = 0; j < 4; j++) {
                acc[j] = make_float4(b1x[j], b1y[j], b1x[j], b1y[j]);
                mma16(acc[j], ah[0], ah[1], ah[2], ah[3], w1h[j][0], w1h[j][1]);
                mma16(acc[j], al[0], al[1], al[2], al[3], w1h[j][0], w1h[j][1]);
                mma16(acc[j], ah[0], ah[1], ah[2], ah[3], w1l[j][0], w1l[j][1]);
            }

            // layer2: p = relu(h) @ W2 + b2; C-frag pairs feed A-frags directly
            float4 p = make_float4(b2x, b2y, b2x, b2y);
#pragma unroll
            for (int s = 0; s < 2; s++) {
                const float4& cA = acc[2 * s];
                const float4& cB = acc[2 * s + 1];
                unsigned a2h[4], a2l[4];
                split_pair(fmaxf(cA.x, 0.0f), fmaxf(cA.y, 0.0f), a2h[0], a2l[0]);
                split_pair(fmaxf(cA.z, 0.0f), fmaxf(cA.w, 0.0f), a2h[1], a2l[1]);
                split_pair(fmaxf(cB.x, 0.0f), fmaxf(cB.y, 0.0f), a2h[2], a2l[2]);
                split_pair(fmaxf(cB.z, 0.0f), fmaxf(cB.w, 0.0f), a2h[3], a2l[3]);
                mma16(p, a2h[0], a2h[1], a2h[2], a2h[3], w2h[s][0], w2h[s][1]);
                mma16(p, a2l[0], a2l[1], a2l[2], a2l[3], w2h[s][0], w2h[s][1]);
                mma16(p, a2h[0], a2h[1], a2h[2], a2h[3], w2l[s][0], w2l[s][1]);
            }
            // p: rows q (x,y) / q+8 (z,w); cols 2tig, 2tig+1

            // cooperative epilogue: 4 tig lanes per reflection
            int iq = 2 * t, iq8 = 2 * t + 1;
            float s0 = softplus_f(p.x), s1 = softplus_f(p.y);
            float s2 = softplus_f(p.z), s3 = softplus_f(p.w);

            float invq  = 1.0f / sg[iq];
            float invq8 = 1.0f / sg[iq8];

            float ip0 = fv[iq].x  * fv[iq].x  * s0, ip1 = fv[iq].y  * fv[iq].y  * s1;
            float ip2 = fv[iq8].x * fv[iq8].x * s2, ip3 = fv[iq8].y * fv[iq8].y * s3;
            float siq  = ip0 + ip1;
            float siq8 = ip2 + ip3;
            float r0q  = (ip0 - io[iq])  * invq,  r1q  = (ip1 - io[iq])  * invq;
            float r0q8 = (ip2 - io[iq8]) * invq8, r1q8 = (ip3 - io[iq8]) * invq8;
            float ssq  = fmaf(r0q,  r0q,  r1q  * r1q);
            float ssq8 = fmaf(r0q8, r0q8, r1q8 * r1q8);

#pragma unroll
            for (int off = 1; off < 4; off <<= 1) {
                siq  += __shfl_xor_sync(0xffffffffu, siq,  off);
                ssq  += __shfl_xor_sync(0xffffffffu, ssq,  off);
                siq8 += __shfl_xor_sync(0xffffffffu, siq8, off);
                ssq8 += __shfl_xor_sync(0xffffffffu, ssq8, off);
            }

            llv[iq] = 0.0f; llv[iq8] = 0.0f;
            imgv[iq] = -1;  imgv[iq8] = -1;
            if (tig == 0) {
                __stcs(out + r[iq],  siq  * 0.125f);
                __stcs(out + r[iq8], siq8 * 0.125f);
                llv[iq]  = fmaf(-0.5f, ssq,  -8.0f * (__logf(sg[iq])  + 0.5f * LOG_2PI_F));
                llv[iq8] = fmaf(-0.5f, ssq8, -8.0f * (__logf(sg[iq8]) + 0.5f * LOG_2PI_F));
                imgv[iq]  = img[iq];
                imgv[iq8] = img[iq8];
            }
        }

        // ======== PHASE 3: image aggregation, one call per reflection slot =====
        seg_atomic(llv[0], imgv[0], lane);
        seg_atomic(llv[1], imgv[1], lane);
        seg_atomic(llv[2], imgv[2], lane);
        seg_atomic(llv[3], imgv[3], lane);
    }

    // ---- fused finalize: last block to finish reduces images + writes scalars --
    __shared__ unsigned s_last;
    __syncthreads();
    if (tid == 0) {
        __threadfence();
        unsigned t = atomicAdd(&g_done, 1u);
        s_last = (t == gridDim.x - 1) ? 1u : 0u;
    }
    __syncthreads();
    if (s_last) {
        float acc = 0.0f;
        for (int i = tid; i < N_IMAGES; i += 128)
            acc += g_img_sum[i] * (1.0f / fmaxf(g_img_cnt[i], 1.0f));
#pragma unroll
        for (int off = 16; off; off >>= 1)
            acc += __shfl_down_sync(0xffffffffu, acc, off);
        __shared__ float wsum[4];
        if (lane == 0) wsum[w] = acc;
        __syncthreads();
        if (tid == 0) {
            float total = wsum[0] + wsum[1] + wsum[2] + wsum[3];
            out[N_REFLNS]     = -(total / (float)MC) / (float)N_IMAGES;
            out[N_REFLNS + 1] = g_kl_sum * (1.0f / (float)N_RAC);
        }
    }
}

// ---------------- launch ----------------
extern "C" void kernel_launch(void* const* d_in, const int* in_sizes, int n_in,
                              void* d_out, int out_size) {
    const float* q_loc     = (const float*)d_in[0];
    const float* q_ls      = (const float*)d_in[1];
    const float* eps       = (const float*)d_in[2];
    const float* metadata  = (const float*)d_in[3];
    const float* W1        = (const float*)d_in[4];
    const float* b1        = (const float*)d_in[5];
    const float* W2        = (const float*)d_in[6];
    const float* b2        = (const float*)d_in[7];
    const float* iobs      = (const float*)d_in[8];
    const float* sigiobs   = (const float*)d_in[9];
    const int*   image_id  = (const int*)d_in[10];
    const int*   miller_id = (const int*)d_in[11];
    float* out = (float*)d_out;

    zkl_kernel<<<(N_RAC + 255) / 256, 256>>>(q_loc, q_ls, eps);
    refl_kernel<<<2368, 128>>>(metadata, W1, b1, W2, b2,
                               iobs, sigiobs, image_id, miller_id, out);
}

// round 12
// speedup vs baseline: 1.6365x; 1.5076x over previous
#include <cuda_runtime.h>
#include <cuda_fp16.h>
#include <cstdint>

#define N_REFLNS 2000000
#define N_IMAGES 8192
#define N_RAC    1000000
#define MC       8
#define D_META   16
#define HIDDEN   32
#define LOG_2PI_F 1.8378770664093453f

// ---------------- scratch (static device globals; no allocation) ----------------
__device__ float4 g_zT[N_RAC * 2];       // z transposed: (N_RAC, 8)
__device__ float  g_img_sum[N_IMAGES];
__device__ float  g_img_cnt[N_IMAGES];
__device__ float  g_kl_sum;
__device__ float  g_ll_total;
__device__ unsigned g_done;

// ---------------- helpers ----------------
__device__ __forceinline__ void split_pair(float x, float y, unsigned& hi, unsigned& lo) {
    __half2 h = __floats2half2_rn(x, y);
    float2 hf = __half22float2(h);
    __half2 l = __floats2half2_rn(x - hf.x, y - hf.y);
    hi = *reinterpret_cast<unsigned*>(&h);
    lo = *reinterpret_cast<unsigned*>(&l);
}

__device__ __forceinline__ void mma16(float4& d,
                                      unsigned a0, unsigned a1, unsigned a2, unsigned a3,
                                      unsigned b0, unsigned b1) {
    asm("mma.sync.aligned.m16n8k16.row.col.f32.f16.f16.f32 "
        "{%0,%1,%2,%3}, {%4,%5,%6,%7}, {%8,%9}, {%0,%1,%2,%3};"
        : "+f"(d.x), "+f"(d.y), "+f"(d.z), "+f"(d.w)
        : "r"(a0), "r"(a1), "r"(a2), "r"(a3), "r"(b0), "r"(b1));
}

__device__ __forceinline__ float softplus_f(float x) {
    float ax = fabsf(x);
    float t  = __expf(-ax);
    float l  = (t > 0.0078125f) ? __logf(1.0f + t) : fmaf(-0.5f * t, t, t);
    return fmaxf(x, 0.0f) + l;
}

// ---------------- kernel 1: init + z transpose + KL ----------------
__global__ __launch_bounds__(256) void zkl_kernel(const float* __restrict__ q_loc,
                                                  const float* __restrict__ q_ls,
                                                  const float* __restrict__ eps) {
    int m = blockIdx.x * 256 + threadIdx.x;
    if (m < N_IMAGES) { g_img_sum[m] = 0.0f; g_img_cnt[m] = 0.0f; }
    if (m == 0) { g_kl_sum = 0.0f; g_ll_total = 0.0f; g_done = 0u; }
    float kl = 0.0f;
    if (m < N_RAC) {
        float loc = q_loc[m];
        float ls  = q_ls[m];
        float s   = __expf(ls);
        kl = fmaf(0.5f, fmaf(s, s, fmaf(loc, loc, -1.0f)), -ls);
        float z[8];
#pragma unroll
        for (int c = 0; c < 8; c++)
            z[c] = fmaf(s, __ldcs(eps + (size_t)c * N_RAC + m), loc);
        g_zT[2 * m]     = make_float4(z[0], z[1], z[2], z[3]);
        g_zT[2 * m + 1] = make_float4(z[4], z[5], z[6], z[7]);
    }
#pragma unroll
    for (int off = 16; off; off >>= 1)
        kl += __shfl_down_sync(0xffffffffu, kl, off);
    __shared__ float wsum[8];
    int lane = threadIdx.x & 31, wid = threadIdx.x >> 5;
    if (lane == 0) wsum[wid] = kl;
    __syncthreads();
    if (threadIdx.x == 0) {
        float t = 0.0f;
#pragma unroll
        for (int i = 0; i < 8; i++) t += wsum[i];
        atomicAdd(&g_kl_sum, t);
    }
}

// segmented warp reduce + atomic (image_id sorted; popc counts reflections/image)
__device__ __forceinline__ void seg_atomic(float v, int img, int lane) {
    unsigned mask = __match_any_sync(0xffffffffu, img);
    int hi = 31 - __clz(mask);
#pragma unroll
    for (int off = 1; off < 32; off <<= 1) {
        float o = __shfl_down_sync(0xffffffffu, v, off);
        if (lane + off <= hi) v += o;
    }
    if (lane == (__ffs(mask) - 1)) {
        atomicAdd(&g_img_sum[img], v);
        atomicAdd(&g_img_cnt[img], (float)__popc(mask));
    }
}

// ---------------- kernel 2: fp16x3 tensor MLP + likelihood, lane-ownership ------
// Lane l owns reflection base+l: 4 coalesced scalar LDGs; shfl distributes to
// MMA groups; owners collect si/ss back for ONE log, ONE coalesced store, and
// ONE seg_atomic per chunk. (R10 lesson: 16 broadcast-redundant LDGs + 4
// seg_atomics + 4 serialized logs were pure issue waste.)
__global__ __launch_bounds__(128, 4) void refl_kernel(const float* __restrict__ metadata,
                                                      const float* __restrict__ W1,
                                                      const float* __restrict__ b1,
                                                      const float* __restrict__ W2,
                                                      const float* __restrict__ b2,
                                                      const float* __restrict__ iobs,
                                                      const float* __restrict__ sigiobs,
                                                      const int*   __restrict__ image_id,
                                                      const int*   __restrict__ miller_id,
                                                      float*       __restrict__ out) {
    const unsigned FULL = 0xffffffffu;
    int tid  = threadIdx.x;
    int w    = tid >> 5;
    int lane = tid & 31;
    int q    = lane >> 2;   // groupID: row within m16
    int tig  = lane & 3;    // thread-in-group

    // ---- weight fragments (hi/lo fp16), loaded once per warp ----
    unsigned w1h[4][2], w1l[4][2];
#pragma unroll
    for (int j = 0; j < 4; j++) {
        int col = 8 * j + q;
        split_pair(W1[(2 * tig) * HIDDEN + col],     W1[(2 * tig + 1) * HIDDEN + col], w1h[j][0], w1l[j][0]);
        split_pair(W1[(2 * tig + 8) * HIDDEN + col], W1[(2 * tig + 9) * HIDDEN + col], w1h[j][1], w1l[j][1]);
    }
    unsigned w2h[2][2], w2l[2][2];
#pragma unroll
    for (int s = 0; s < 2; s++) {
        int k0 = 16 * s + 2 * tig;
        split_pair(W2[k0 * MC + q],       W2[(k0 + 1) * MC + q], w2h[s][0], w2l[s][0]);
        split_pair(W2[(k0 + 8) * MC + q], W2[(k0 + 9) * MC + q], w2h[s][1], w2l[s][1]);
    }
    float b1x[4], b1y[4];
#pragma unroll
    for (int j = 0; j < 4; j++) { b1x[j] = b1[8 * j + 2 * tig]; b1y[j] = b1[8 * j + 2 * tig + 1]; }
    float b2x = b2[2 * tig], b2y = b2[2 * tig + 1];

    const float* zTf = (const float*)g_zT;
    const int nchunks = N_REFLNS / 32;     // 62500 exact
    int gwarp  = blockIdx.x * 4 + w;
    int nwarps = gridDim.x * 4;

    // owner-collect constants
    int src_grp = 4 * (lane & 7);          // tig=0 lane of my reflection's group
    int isel    = lane >> 3;               // which slot (0..3) my reflection is

    for (int chunk = gwarp; chunk < nchunks; chunk += nwarps) {
        int base = chunk * 32;
        int rown = base + lane;

        // ---- owner loads: fully coalesced, zero redundancy ----
        int   mid_own = __ldcs(miller_id + rown);
        float io_own  = __ldcs(iobs + rown);
        float sg_own  = __ldcs(sigiobs + rown);
        int   img_own = __ldcs(image_id + rown);

        // ---- metadata loads (coalesced LDG.64 stream, evict-first) ----
        float2 va[2][4];
#pragma unroll
        for (int t = 0; t < 2; t++) {
            const float* Ma = metadata + (size_t)(base + 16 * t + q) * D_META;
            const float* Mb = metadata + (size_t)(base + 16 * t + q + 8) * D_META;
            va[t][0] = __ldcs((const float2*)(Ma + 2 * tig));
            va[t][1] = __ldcs((const float2*)(Mb + 2 * tig));
            va[t][2] = __ldcs((const float2*)(Ma + 2 * tig + 8));
            va[t][3] = __ldcs((const float2*)(Mb + 2 * tig + 8));
        }

        // ---- distribute mid to groups, issue gathers early (overlap MLP) ----
        float2 fv[4];
#pragma unroll
        for (int i = 0; i < 4; i++) {
            int mid_i = __shfl_sync(FULL, mid_own, q + 8 * i);
            fv[i] = *(const float2*)(zTf + (size_t)mid_i * 8 + 2 * tig);
        }

        // ---- compute both subtiles ----
        float siv[4], ssv[4];
#pragma unroll
        for (int t = 0; t < 2; t++) {
            unsigned ah[4], al[4];
            split_pair(va[t][0].x, va[t][0].y, ah[0], al[0]);
            split_pair(va[t][1].x, va[t][1].y, ah[1], al[1]);
            split_pair(va[t][2].x, va[t][2].y, ah[2], al[2]);
            split_pair(va[t][3].x, va[t][3].y, ah[3], al[3]);

            // layer1: h = meta @ W1 + b1, 3-term fp16
            float4 acc[4];
#pragma unroll
            for (int j = 0; j < 4; j++) {
                acc[j] = make_float4(b1x[j], b1y[j], b1x[j], b1y[j]);
                mma16(acc[j], ah[0], ah[1], ah[2], ah[3], w1h[j][0], w1h[j][1]);
                mma16(acc[j], al[0], al[1], al[2], al[3], w1h[j][0], w1h[j][1]);
                mma16(acc[j], ah[0], ah[1], ah[2], ah[3], w1l[j][0], w1l[j][1]);
            }

            // layer2: p = relu(h) @ W2 + b2; C-frag pairs feed A-frags directly
            float4 p = make_float4(b2x, b2y, b2x, b2y);
#pragma unroll
            for (int s = 0; s < 2; s++) {
                const float4& cA = acc[2 * s];
                const float4& cB = acc[2 * s + 1];
                unsigned a2h[4], a2l[4];
                split_pair(fmaxf(cA.x, 0.0f), fmaxf(cA.y, 0.0f), a2h[0], a2l[0]);
                split_pair(fmaxf(cA.z, 0.0f), fmaxf(cA.w, 0.0f), a2h[1], a2l[1]);
                split_pair(fmaxf(cB.x, 0.0f), fmaxf(cB.y, 0.0f), a2h[2], a2l[2]);
                split_pair(fmaxf(cB.z, 0.0f), fmaxf(cB.w, 0.0f), a2h[3], a2l[3]);
                mma16(p, a2h[0], a2h[1], a2h[2], a2h[3], w2h[s][0], w2h[s][1]);
                mma16(p, a2l[0], a2l[1], a2l[2], a2l[3], w2h[s][0], w2h[s][1]);
                mma16(p, a2h[0], a2h[1], a2h[2], a2h[3], w2l[s][0], w2l[s][1]);
            }
            // p: rows q (x,y) / q+8 (z,w); cols 2tig, 2tig+1

            // epilogue: shfl io/sg from owners (no redundant LDGs)
            int iq = 2 * t, iq8 = 2 * t + 1;
            float io_a = __shfl_sync(FULL, io_own, q + 8 * iq);
            float io_b = __shfl_sync(FULL, io_own, q + 8 * iq8);
            float sg_a = __shfl_sync(FULL, sg_own, q + 8 * iq);
            float sg_b = __shfl_sync(FULL, sg_own, q + 8 * iq8);

            float s0 = softplus_f(p.x), s1 = softplus_f(p.y);
            float s2 = softplus_f(p.z), s3 = softplus_f(p.w);

            float inva = 1.0f / sg_a;
            float invb = 1.0f / sg_b;

            float ip0 = fv[iq].x  * fv[iq].x  * s0, ip1 = fv[iq].y  * fv[iq].y  * s1;
            float ip2 = fv[iq8].x * fv[iq8].x * s2, ip3 = fv[iq8].y * fv[iq8].y * s3;
            float sia = ip0 + ip1;
            float sib = ip2 + ip3;
            float r0a = (ip0 - io_a) * inva, r1a = (ip1 - io_a) * inva;
            float r0b = (ip2 - io_b) * invb, r1b = (ip3 - io_b) * invb;
            float ssa = fmaf(r0a, r0a, r1a * r1a);
            float ssb = fmaf(r0b, r0b, r1b * r1b);

#pragma unroll
            for (int off = 1; off < 4; off <<= 1) {
                sia += __shfl_xor_sync(FULL, sia, off);
                ssa += __shfl_xor_sync(FULL, ssa, off);
                sib += __shfl_xor_sync(FULL, sib, off);
                ssb += __shfl_xor_sync(FULL, ssb, off);
            }
            siv[iq] = sia; ssv[iq] = ssa;
            siv[iq8] = sib; ssv[iq8] = ssb;
        }

        // ---- owner collect: fetch my reflection's si/ss from its group ----
        float c0 = __shfl_sync(FULL, siv[0], src_grp);
        float c1 = __shfl_sync(FULL, siv[1], src_grp);
        float c2 = __shfl_sync(FULL, siv[2], src_grp);
        float c3 = __shfl_sync(FULL, siv[3], src_grp);
        float si_own = (isel < 2) ? (isel == 0 ? c0 : c1) : (isel == 2 ? c2 : c3);
        float d0 = __shfl_sync(FULL, ssv[0], src_grp);
        float d1 = __shfl_sync(FULL, ssv[1], src_grp);
        float d2 = __shfl_sync(FULL, ssv[2], src_grp);
        float d3 = __shfl_sync(FULL, ssv[3], src_grp);
        float ss_own = (isel < 2) ? (isel == 0 ? d0 : d1) : (isel == 2 ? d2 : d3);

        // ONE coalesced store, ONE log, ONE seg_atomic
        __stcs(out + rown, si_own * 0.125f);
        float ll = fmaf(-0.5f, ss_own, -8.0f * (__logf(sg_own) + 0.5f * LOG_2PI_F));
        seg_atomic(ll, img_own, lane);
    }
}

// ---------------- kernel 3: parallel finalize (8 blocks, last writes scalars) ---
__global__ __launch_bounds__(1024) void finalize_kernel(float* __restrict__ out) {
    int i = blockIdx.x * 1024 + threadIdx.x;
    float v = g_img_sum[i] * (1.0f / fmaxf(g_img_cnt[i], 1.0f));
#pragma unroll
    for (int off = 16; off; off >>= 1)
        v += __shfl_down_sync(0xffffffffu, v, off);
    __shared__ float wsum[32];
    int lane = threadIdx.x & 31, wid = threadIdx.x >> 5;
    if (lane == 0) wsum[wid] = v;
    __syncthreads();
    if (wid == 0) {
        float t = wsum[lane];
#pragma unroll
        for (int off = 16; off; off >>= 1)
            t += __shfl_down_sync(0xffffffffu, t, off);
        if (lane == 0) {
            atomicAdd(&g_ll_total, t);
            __threadfence();
            unsigned ticket = atomicAdd(&g_done, 1u);
            if (ticket == gridDim.x - 1) {
                float total = atomicAdd(&g_ll_total, 0.0f);
                out[N_REFLNS]     = -(total / (float)MC) / (float)N_IMAGES;
                out[N_REFLNS + 1] = g_kl_sum * (1.0f / (float)N_RAC);
            }
        }
    }
}

// ---------------- launch ----------------
extern "C" void kernel_launch(void* const* d_in, const int* in_sizes, int n_in,
                              void* d_out, int out_size) {
    const float* q_loc     = (const float*)d_in[0];
    const float* q_ls      = (const float*)d_in[1];
    const float* eps       = (const float*)d_in[2];
    const float* metadata  = (const float*)d_in[3];
    const float* W1        = (const float*)d_in[4];
    const float* b1        = (const float*)d_in[5];
    const float* W2        = (const float*)d_in[6];
    const float* b2        = (const float*)d_in[7];
    const float* iobs      = (const float*)d_in[8];
    const float* sigiobs   = (const float*)d_in[9];
    const int*   image_id  = (const int*)d_in[10];
    const int*   miller_id = (const int*)d_in[11];
    float* out = (float*)d_out;

    zkl_kernel<<<(N_RAC + 255) / 256, 256>>>(q_loc, q_ls, eps);
    refl_kernel<<<2368, 128>>>(metadata, W1, b1, W2, b2,
                               iobs, sigiobs, image_id, miller_id, out);
    finalize_kernel<<<N_IMAGES / 1024, 1024>>>(out);
}

// round 13
// speedup vs baseline: 1.6739x; 1.0228x over previous
#include <cuda_runtime.h>
#include <cuda_fp16.h>
#include <cstdint>

#define N_REFLNS 2000000
#define N_IMAGES 8192
#define N_RAC    1000000
#define MC       8
#define D_META   16
#define HIDDEN   32
#define LOG_2PI_F 1.8378770664093453f

// ---------------- scratch (static device globals; no allocation) ----------------
__device__ float4 g_zT[N_RAC * 2];       // z transposed: (N_RAC, 8)
__device__ float  g_img_sum[N_IMAGES];
__device__ float  g_img_cnt[N_IMAGES];
__device__ float  g_kl_sum;
__device__ float  g_ll_total;
__device__ unsigned g_done;

// ---------------- helpers ----------------
__device__ __forceinline__ void split_pair(float x, float y, unsigned& hi, unsigned& lo) {
    __half2 h = __floats2half2_rn(x, y);
    float2 hf = __half22float2(h);
    __half2 l = __floats2half2_rn(x - hf.x, y - hf.y);
    hi = *reinterpret_cast<unsigned*>(&h);
    lo = *reinterpret_cast<unsigned*>(&l);
}

__device__ __forceinline__ void mma16(float4& d,
                                      unsigned a0, unsigned a1, unsigned a2, unsigned a3,
                                      unsigned b0, unsigned b1) {
    asm("mma.sync.aligned.m16n8k16.row.col.f32.f16.f16.f32 "
        "{%0,%1,%2,%3}, {%4,%5,%6,%7}, {%8,%9}, {%0,%1,%2,%3};"
        : "+f"(d.x), "+f"(d.y), "+f"(d.z), "+f"(d.w)
        : "r"(a0), "r"(a1), "r"(a2), "r"(a3), "r"(b0), "r"(b1));
}

__device__ __forceinline__ float softplus_f(float x) {
    float ax = fabsf(x);
    float t  = __expf(-ax);
    float l  = (t > 0.0078125f) ? __logf(1.0f + t) : fmaf(-0.5f * t, t, t);
    return fmaxf(x, 0.0f) + l;
}

// ---------------- kernel 1: init + z transpose + KL ----------------
__global__ __launch_bounds__(256) void zkl_kernel(const float* __restrict__ q_loc,
                                                  const float* __restrict__ q_ls,
                                                  const float* __restrict__ eps) {
    int m = blockIdx.x * 256 + threadIdx.x;
    if (m < N_IMAGES) { g_img_sum[m] = 0.0f; g_img_cnt[m] = 0.0f; }
    if (m == 0) { g_kl_sum = 0.0f; g_ll_total = 0.0f; g_done = 0u; }
    float kl = 0.0f;
    if (m < N_RAC) {
        float loc = q_loc[m];
        float ls  = q_ls[m];
        float s   = __expf(ls);
        kl = fmaf(0.5f, fmaf(s, s, fmaf(loc, loc, -1.0f)), -ls);
        float z[8];
#pragma unroll
        for (int c = 0; c < 8; c++)
            z[c] = fmaf(s, __ldcs(eps + (size_t)c * N_RAC + m), loc);
        g_zT[2 * m]     = make_float4(z[0], z[1], z[2], z[3]);
        g_zT[2 * m + 1] = make_float4(z[4], z[5], z[6], z[7]);
    }
#pragma unroll
    for (int off = 16; off; off >>= 1)
        kl += __shfl_down_sync(0xffffffffu, kl, off);
    __shared__ float wsum[8];
    int lane = threadIdx.x & 31, wid = threadIdx.x >> 5;
    if (lane == 0) wsum[wid] = kl;
    __syncthreads();
    if (threadIdx.x == 0) {
        float t = 0.0f;
#pragma unroll
        for (int i = 0; i < 8; i++) t += wsum[i];
        atomicAdd(&g_kl_sum, t);
    }
}

// segmented warp reduce + atomic (image_id sorted; popc counts reflections/image)
__device__ __forceinline__ void seg_atomic(float v, int img, int lane) {
    unsigned mask = __match_any_sync(0xffffffffu, img);
    int hi = 31 - __clz(mask);
#pragma unroll
    for (int off = 1; off < 32; off <<= 1) {
        float o = __shfl_down_sync(0xffffffffu, v, off);
        if (lane + off <= hi) v += o;
    }
    if (lane == (__ffs(mask) - 1)) {
        atomicAdd(&g_img_sum[img], v);
        atomicAdd(&g_img_cnt[img], (float)__popc(mask));
    }
}

// ---------------- kernel 2: fp16x3 tensor MLP + likelihood, lane-ownership ------
// R11 structure; single change: occupancy 4 -> 5 blocks/SM (102-reg budget).
__global__ __launch_bounds__(128, 5) void refl_kernel(const float* __restrict__ metadata,
                                                      const float* __restrict__ W1,
                                                      const float* __restrict__ b1,
                                                      const float* __restrict__ W2,
                                                      const float* __restrict__ b2,
                                                      const float* __restrict__ iobs,
                                                      const float* __restrict__ sigiobs,
                                                      const int*   __restrict__ image_id,
                                                      const int*   __restrict__ miller_id,
                                                      float*       __restrict__ out) {
    const unsigned FULL = 0xffffffffu;
    int tid  = threadIdx.x;
    int w    = tid >> 5;
    int lane = tid & 31;
    int q    = lane >> 2;   // groupID: row within m16
    int tig  = lane & 3;    // thread-in-group

    // ---- weight fragments (hi/lo fp16), loaded once per warp ----
    unsigned w1h[4][2], w1l[4][2];
#pragma unroll
    for (int j = 0; j < 4; j++) {
        int col = 8 * j + q;
        split_pair(W1[(2 * tig) * HIDDEN + col],     W1[(2 * tig + 1) * HIDDEN + col], w1h[j][0], w1l[j][0]);
        split_pair(W1[(2 * tig + 8) * HIDDEN + col], W1[(2 * tig + 9) * HIDDEN + col], w1h[j][1], w1l[j][1]);
    }
    unsigned w2h[2][2], w2l[2][2];
#pragma unroll
    for (int s = 0; s < 2; s++) {
        int k0 = 16 * s + 2 * tig;
        split_pair(W2[k0 * MC + q],       W2[(k0 + 1) * MC + q], w2h[s][0], w2l[s][0]);
        split_pair(W2[(k0 + 8) * MC + q], W2[(k0 + 9) * MC + q], w2h[s][1], w2l[s][1]);
    }
    float b1x[4], b1y[4];
#pragma unroll
    for (int j = 0; j < 4; j++) { b1x[j] = b1[8 * j + 2 * tig]; b1y[j] = b1[8 * j + 2 * tig + 1]; }
    float b2x = b2[2 * tig], b2y = b2[2 * tig + 1];

    const float* zTf = (const float*)g_zT;
    const int nchunks = N_REFLNS / 32;     // 62500 exact
    int gwarp  = blockIdx.x * 4 + w;
    int nwarps = gridDim.x * 4;

    // owner-collect constants
    int src_grp = 4 * (lane & 7);          // tig=0 lane of my reflection's group
    int isel    = lane >> 3;               // which slot (0..3) my reflection is

    for (int chunk = gwarp; chunk < nchunks; chunk += nwarps) {
        int base = chunk * 32;
        int rown = base + lane;

        // ---- owner loads: fully coalesced, zero redundancy ----
        int   mid_own = __ldcs(miller_id + rown);
        float io_own  = __ldcs(iobs + rown);
        float sg_own  = __ldcs(sigiobs + rown);
        int   img_own = __ldcs(image_id + rown);

        // ---- metadata loads (coalesced LDG.64 stream, evict-first) ----
        float2 va[2][4];
#pragma unroll
        for (int t = 0; t < 2; t++) {
            const float* Ma = metadata + (size_t)(base + 16 * t + q) * D_META;
            const float* Mb = metadata + (size_t)(base + 16 * t + q + 8) * D_META;
            va[t][0] = __ldcs((const float2*)(Ma + 2 * tig));
            va[t][1] = __ldcs((const float2*)(Mb + 2 * tig));
            va[t][2] = __ldcs((const float2*)(Ma + 2 * tig + 8));
            va[t][3] = __ldcs((const float2*)(Mb + 2 * tig + 8));
        }

        // ---- distribute mid to groups, issue gathers early (overlap MLP) ----
        float2 fv[4];
#pragma unroll
        for (int i = 0; i < 4; i++) {
            int mid_i = __shfl_sync(FULL, mid_own, q + 8 * i);
            fv[i] = *(const float2*)(zTf + (size_t)mid_i * 8 + 2 * tig);
        }

        // ---- compute both subtiles ----
        float siv[4], ssv[4];
#pragma unroll
        for (int t = 0; t < 2; t++) {
            unsigned ah[4], al[4];
            split_pair(va[t][0].x, va[t][0].y, ah[0], al[0]);
            split_pair(va[t][1].x, va[t][1].y, ah[1], al[1]);
            split_pair(va[t][2].x, va[t][2].y, ah[2], al[2]);
            split_pair(va[t][3].x, va[t][3].y, ah[3], al[3]);

            // layer1: h = meta @ W1 + b1, 3-term fp16
            float4 acc[4];
#pragma unroll
            for (int j = 0; j < 4; j++) {
                acc[j] = make_float4(b1x[j], b1y[j], b1x[j], b1y[j]);
                mma16(acc[j], ah[0], ah[1], ah[2], ah[3], w1h[j][0], w1h[j][1]);
                mma16(acc[j], al[0], al[1], al[2], al[3], w1h[j][0], w1h[j][1]);
                mma16(acc[j], ah[0], ah[1], ah[2], ah[3], w1l[j][0], w1l[j][1]);
            }

            // layer2: p = relu(h) @ W2 + b2; C-frag pairs feed A-frags directly
            float4 p = make_float4(b2x, b2y, b2x, b2y);
#pragma unroll
            for (int s = 0; s < 2; s++) {
                const float4& cA = acc[2 * s];
                const float4& cB = acc[2 * s + 1];
                unsigned a2h[4], a2l[4];
                split_pair(fmaxf(cA.x, 0.0f), fmaxf(cA.y, 0.0f), a2h[0], a2l[0]);
                split_pair(fmaxf(cA.z, 0.0f), fmaxf(cA.w, 0.0f), a2h[1], a2l[1]);
                split_pair(fmaxf(cB.x, 0.0f), fmaxf(cB.y, 0.0f), a2h[2], a2l[2]);
                split_pair(fmaxf(cB.z, 0.0f), fmaxf(cB.w, 0.0f), a2h[3], a2l[3]);
                mma16(p, a2h[0], a2h[1], a2h[2], a2h[3], w2h[s][0], w2h[s][1]);
                mma16(p, a2l[0], a2l[1], a2l[2], a2l[3], w2h[s][0], w2h[s][1]);
                mma16(p, a2h[0], a2h[1], a2h[2], a2h[3], w2l[s][0], w2l[s][1]);
            }
            // p: rows q (x,y) / q+8 (z,w); cols 2tig, 2tig+1

            // epilogue: shfl io/sg from owners (no redundant LDGs)
            int iq = 2 * t, iq8 = 2 * t + 1;
            float io_a = __shfl_sync(FULL, io_own, q + 8 * iq);
            float io_b = __shfl_sync(FULL, io_own, q + 8 * iq8);
            float sg_a = __shfl_sync(FULL, sg_own, q + 8 * iq);
            float sg_b = __shfl_sync(FULL, sg_own, q + 8 * iq8);

            float s0 = softplus_f(p.x), s1 = softplus_f(p.y);
            float s2 = softplus_f(p.z), s3 = softplus_f(p.w);

            float inva = 1.0f / sg_a;
            float invb = 1.0f / sg_b;

            float ip0 = fv[iq].x  * fv[iq].x  * s0, ip1 = fv[iq].y  * fv[iq].y  * s1;
            float ip2 = fv[iq8].x * fv[iq8].x * s2, ip3 = fv[iq8].y * fv[iq8].y * s3;
            float sia = ip0 + ip1;
            float sib = ip2 + ip3;
            float r0a = (ip0 - io_a) * inva, r1a = (ip1 - io_a) * inva;
            float r0b = (ip2 - io_b) * invb, r1b = (ip3 - io_b) * invb;
            float ssa = fmaf(r0a, r0a, r1a * r1a);
            float ssb = fmaf(r0b, r0b, r1b * r1b);

#pragma unroll
            for (int off = 1; off < 4; off <<= 1) {
                sia += __shfl_xor_sync(FULL, sia, off);
                ssa += __shfl_xor_sync(FULL, ssa, off);
                sib += __shfl_xor_sync(FULL, sib, off);
                ssb += __shfl_xor_sync(FULL, ssb, off);
            }
            siv[iq] = sia; ssv[iq] = ssa;
            siv[iq8] = sib; ssv[iq8] = ssb;
        }

        // ---- owner collect: fetch my reflection's si/ss from its group ----
        float c0 = __shfl_sync(FULL, siv[0], src_grp);
        float c1 = __shfl_sync(FULL, siv[1], src_grp);
        float c2 = __shfl_sync(FULL, siv[2], src_grp);
        float c3 = __shfl_sync(FULL, siv[3], src_grp);
        float si_own = (isel < 2) ? (isel == 0 ? c0 : c1) : (isel == 2 ? c2 : c3);
        float d0 = __shfl_sync(FULL, ssv[0], src_grp);
        float d1 = __shfl_sync(FULL, ssv[1], src_grp);
        float d2 = __shfl_sync(FULL, ssv[2], src_grp);
        float d3 = __shfl_sync(FULL, ssv[3], src_grp);
        float ss_own = (isel < 2) ? (isel == 0 ? d0 : d1) : (isel == 2 ? d2 : d3);

        // ONE coalesced store, ONE log, ONE seg_atomic
        __stcs(out + rown, si_own * 0.125f);
        float ll = fmaf(-0.5f, ss_own, -8.0f * (__logf(sg_own) + 0.5f * LOG_2PI_F));
        seg_atomic(ll, img_own, lane);
    }
}

// ---------------- kernel 3: parallel finalize (8 blocks, last writes scalars) ---
__global__ __launch_bounds__(1024) void finalize_kernel(float* __restrict__ out) {
    int i = blockIdx.x * 1024 + threadIdx.x;
    float v = g_img_sum[i] * (1.0f / fmaxf(g_img_cnt[i], 1.0f));
#pragma unroll
    for (int off = 16; off; off >>= 1)
        v += __shfl_down_sync(0xffffffffu, v, off);
    __shared__ float wsum[32];
    int lane = threadIdx.x & 31, wid = threadIdx.x >> 5;
    if (lane == 0) wsum[wid] = v;
    __syncthreads();
    if (wid == 0) {
        float t = wsum[lane];
#pragma unroll
        for (int off = 16; off; off >>= 1)
            t += __shfl_down_sync(0xffffffffu, t, off);
        if (lane == 0) {
            atomicAdd(&g_ll_total, t);
            __threadfence();
            unsigned ticket = atomicAdd(&g_done, 1u);
            if (ticket == gridDim.x - 1) {
                float total = atomicAdd(&g_ll_total, 0.0f);
                out[N_REFLNS]     = -(total / (float)MC) / (float)N_IMAGES;
                out[N_REFLNS + 1] = g_kl_sum * (1.0f / (float)N_RAC);
            }
        }
    }
}

// ---------------- launch ----------------
extern "C" void kernel_launch(void* const* d_in, const int* in_sizes, int n_in,
                              void* d_out, int out_size) {
    const float* q_loc     = (const float*)d_in[0];
    const float* q_ls      = (const float*)d_in[1];
    const float* eps       = (const float*)d_in[2];
    const float* metadata  = (const float*)d_in[3];
    const float* W1        = (const float*)d_in[4];
    const float* b1        = (const float*)d_in[5];
    const float* W2        = (const float*)d_in[6];
    const float* b2        = (const float*)d_in[7];
    const float* iobs      = (const float*)d_in[8];
    const float* sigiobs   = (const float*)d_in[9];
    const int*   image_id  = (const int*)d_in[10];
    const int*   miller_id = (const int*)d_in[11];
    float* out = (float*)d_out;

    zkl_kernel<<<(N_RAC + 255) / 256, 256>>>(q_loc, q_ls, eps);
    refl_kernel<<<2960, 128>>>(metadata, W1, b1, W2, b2,
                               iobs, sigiobs, image_id, miller_id, out);
    finalize_kernel<<<N_IMAGES / 1024, 1024>>>(out);
}

// round 14
// speedup vs baseline: 1.7928x; 1.0711x over previous
#include <cuda_runtime.h>
#include <cuda_fp16.h>
#include <cstdint>

#define N_REFLNS 2000000
#define N_IMAGES 8192
#define N_RAC    1000000
#define MC       8
#define D_META   16
#define HIDDEN   32
#define LOG_2PI_F 1.8378770664093453f

// ---------------- scratch (static device globals; no allocation) ----------------
__device__ float4 g_zT[N_RAC * 2];       // z transposed: (N_RAC, 8)
__device__ float  g_img_sum[N_IMAGES];
__device__ float  g_img_cnt[N_IMAGES];
__device__ float  g_kl_sum;
__device__ float  g_ll_total;
__device__ unsigned g_done;

// ---------------- helpers ----------------
__device__ __forceinline__ void split_pair(float x, float y, unsigned& hi, unsigned& lo) {
    __half2 h = __floats2half2_rn(x, y);
    float2 hf = __half22float2(h);
    __half2 l = __floats2half2_rn(x - hf.x, y - hf.y);
    hi = *reinterpret_cast<unsigned*>(&h);
    lo = *reinterpret_cast<unsigned*>(&l);
}

__device__ __forceinline__ void mma16(float4& d,
                                      unsigned a0, unsigned a1, unsigned a2, unsigned a3,
                                      unsigned b0, unsigned b1) {
    asm("mma.sync.aligned.m16n8k16.row.col.f32.f16.f16.f32 "
        "{%0,%1,%2,%3}, {%4,%5,%6,%7}, {%8,%9}, {%0,%1,%2,%3};"
        : "+f"(d.x), "+f"(d.y), "+f"(d.z), "+f"(d.w)
        : "r"(a0), "r"(a1), "r"(a2), "r"(a3), "r"(b0), "r"(b1));
}

__device__ __forceinline__ float softplus_f(float x) {
    float ax = fabsf(x);
    float t  = __expf(-ax);
    float l  = (t > 0.0078125f) ? __logf(1.0f + t) : fmaf(-0.5f * t, t, t);
    return fmaxf(x, 0.0f) + l;
}

// ---------------- kernel 1: init + z transpose + KL ----------------
__global__ __launch_bounds__(256) void zkl_kernel(const float* __restrict__ q_loc,
                                                  const float* __restrict__ q_ls,
                                                  const float* __restrict__ eps) {
    int m = blockIdx.x * 256 + threadIdx.x;
    if (m < N_IMAGES) { g_img_sum[m] = 0.0f; g_img_cnt[m] = 0.0f; }
    if (m == 0) { g_kl_sum = 0.0f; g_ll_total = 0.0f; g_done = 0u; }
    float kl = 0.0f;
    if (m < N_RAC) {
        float loc = q_loc[m];
        float ls  = q_ls[m];
        float s   = __expf(ls);
        kl = fmaf(0.5f, fmaf(s, s, fmaf(loc, loc, -1.0f)), -ls);
        float z[8];
#pragma unroll
        for (int c = 0; c < 8; c++)
            z[c] = fmaf(s, __ldcs(eps + (size_t)c * N_RAC + m), loc);
        g_zT[2 * m]     = make_float4(z[0], z[1], z[2], z[3]);
        g_zT[2 * m + 1] = make_float4(z[4], z[5], z[6], z[7]);
    }
#pragma unroll
    for (int off = 16; off; off >>= 1)
        kl += __shfl_down_sync(0xffffffffu, kl, off);
    __shared__ float wsum[8];
    int lane = threadIdx.x & 31, wid = threadIdx.x >> 5;
    if (lane == 0) wsum[wid] = kl;
    __syncthreads();
    if (threadIdx.x == 0) {
        float t = 0.0f;
#pragma unroll
        for (int i = 0; i < 8; i++) t += wsum[i];
        atomicAdd(&g_kl_sum, t);
    }
}

// segmented warp reduce + atomic (image_id sorted; popc counts reflections/image)
__device__ __forceinline__ void seg_atomic(float v, int img, int lane) {
    unsigned mask = __match_any_sync(0xffffffffu, img);
    int hi = 31 - __clz(mask);
#pragma unroll
    for (int off = 1; off < 32; off <<= 1) {
        float o = __shfl_down_sync(0xffffffffu, v, off);
        if (lane + off <= hi) v += o;
    }
    if (lane == (__ffs(mask) - 1)) {
        atomicAdd(&g_img_sum[img], v);
        atomicAdd(&g_img_cnt[img], (float)__popc(mask));
    }
}

// ---------------- kernel 2: fp16x3 tensor MLP + SMEM-transpose epilogue ---------
// R12 MMA core; epilogue restructured: p staged via per-warp SMEM so each lane
// owns its reflection end-to-end. Replaces ~36 shfl + selects with 4 STS + 2 LDS.
#define PB_STRIDE 12   // floats; 48B row stride, float4-aligned

__global__ __launch_bounds__(128, 5) void refl_kernel(const float* __restrict__ metadata,
                                                      const float* __restrict__ W1,
                                                      const float* __restrict__ b1,
                                                      const float* __restrict__ W2,
                                                      const float* __restrict__ b2,
                                                      const float* __restrict__ iobs,
                                                      const float* __restrict__ sigiobs,
                                                      const int*   __restrict__ image_id,
                                                      const int*   __restrict__ miller_id,
                                                      float*       __restrict__ out) {
    __shared__ __align__(16) float pbuf[4][32 * PB_STRIDE];

    int tid  = threadIdx.x;
    int w    = tid >> 5;
    int lane = tid & 31;
    int q    = lane >> 2;   // groupID: row within m16
    int tig  = lane & 3;    // thread-in-group
    float* pb = pbuf[w];

    // ---- weight fragments (hi/lo fp16), loaded once per warp ----
    unsigned w1h[4][2], w1l[4][2];
#pragma unroll
    for (int j = 0; j < 4; j++) {
        int col = 8 * j + q;
        split_pair(W1[(2 * tig) * HIDDEN + col],     W1[(2 * tig + 1) * HIDDEN + col], w1h[j][0], w1l[j][0]);
        split_pair(W1[(2 * tig + 8) * HIDDEN + col], W1[(2 * tig + 9) * HIDDEN + col], w1h[j][1], w1l[j][1]);
    }
    unsigned w2h[2][2], w2l[2][2];
#pragma unroll
    for (int s = 0; s < 2; s++) {
        int k0 = 16 * s + 2 * tig;
        split_pair(W2[k0 * MC + q],       W2[(k0 + 1) * MC + q], w2h[s][0], w2l[s][0]);
        split_pair(W2[(k0 + 8) * MC + q], W2[(k0 + 9) * MC + q], w2h[s][1], w2l[s][1]);
    }
    float b1x[4], b1y[4];
#pragma unroll
    for (int j = 0; j < 4; j++) { b1x[j] = b1[8 * j + 2 * tig]; b1y[j] = b1[8 * j + 2 * tig + 1]; }
    float b2x = b2[2 * tig], b2y = b2[2 * tig + 1];

    const int nchunks = N_REFLNS / 32;     // 62500 exact
    int gwarp  = blockIdx.x * 4 + w;
    int nwarps = gridDim.x * 4;

    for (int chunk = gwarp; chunk < nchunks; chunk += nwarps) {
        int base = chunk * 32;
        int rown = base + lane;

        // ---- owner loads: fully coalesced, zero redundancy ----
        int   mid_own = __ldcs(miller_id + rown);
        float io_own  = __ldcs(iobs + rown);
        float sg_own  = __ldcs(sigiobs + rown);
        int   img_own = __ldcs(image_id + rown);

        // ---- metadata loads (coalesced LDG.64 stream, evict-first) ----
        float2 va[2][4];
#pragma unroll
        for (int t = 0; t < 2; t++) {
            const float* Ma = metadata + (size_t)(base + 16 * t + q) * D_META;
            const float* Mb = metadata + (size_t)(base + 16 * t + q + 8) * D_META;
            va[t][0] = __ldcs((const float2*)(Ma + 2 * tig));
            va[t][1] = __ldcs((const float2*)(Mb + 2 * tig));
            va[t][2] = __ldcs((const float2*)(Ma + 2 * tig + 8));
            va[t][3] = __ldcs((const float2*)(Mb + 2 * tig + 8));
        }

        // ---- zT gather: owner-contiguous 32B (2x LDG.128), overlaps the MLP ----
        float4 f0 = g_zT[2 * mid_own];
        float4 f1 = g_zT[2 * mid_own + 1];

        // ---- compute both subtiles, stage p into per-warp SMEM ----
#pragma unroll
        for (int t = 0; t < 2; t++) {
            unsigned ah[4], al[4];
            split_pair(va[t][0].x, va[t][0].y, ah[0], al[0]);
            split_pair(va[t][1].x, va[t][1].y, ah[1], al[1]);
            split_pair(va[t][2].x, va[t][2].y, ah[2], al[2]);
            split_pair(va[t][3].x, va[t][3].y, ah[3], al[3]);

            // layer1: h = meta @ W1 + b1, 3-term fp16
            float4 acc[4];
#pragma unroll
            for (int j = 0; j < 4; j++) {
                acc[j] = make_float4(b1x[j], b1y[j], b1x[j], b1y[j]);
                mma16(acc[j], ah[0], ah[1], ah[2], ah[3], w1h[j][0], w1h[j][1]);
                mma16(acc[j], al[0], al[1], al[2], al[3], w1h[j][0], w1h[j][1]);
                mma16(acc[j], ah[0], ah[1], ah[2], ah[3], w1l[j][0], w1l[j][1]);
            }

            // layer2: p = relu(h) @ W2 + b2; C-frag pairs feed A-frags directly
            float4 p = make_float4(b2x, b2y, b2x, b2y);
#pragma unroll
            for (int s = 0; s < 2; s++) {
                const float4& cA = acc[2 * s];
                const float4& cB = acc[2 * s + 1];
                unsigned a2h[4], a2l[4];
                split_pair(fmaxf(cA.x, 0.0f), fmaxf(cA.y, 0.0f), a2h[0], a2l[0]);
                split_pair(fmaxf(cA.z, 0.0f), fmaxf(cA.w, 0.0f), a2h[1], a2l[1]);
                split_pair(fmaxf(cB.x, 0.0f), fmaxf(cB.y, 0.0f), a2h[2], a2l[2]);
                split_pair(fmaxf(cB.z, 0.0f), fmaxf(cB.w, 0.0f), a2h[3], a2l[3]);
                mma16(p, a2h[0], a2h[1], a2h[2], a2h[3], w2h[s][0], w2h[s][1]);
                mma16(p, a2l[0], a2l[1], a2l[2], a2l[3], w2h[s][0], w2h[s][1]);
                mma16(p, a2h[0], a2h[1], a2h[2], a2h[3], w2l[s][0], w2l[s][1]);
            }
            // p: rows 16t+q (x,y) / 16t+q+8 (z,w); cols 2tig, 2tig+1
            *(float2*)&pb[(16 * t + q) * PB_STRIDE + 2 * tig]     = make_float2(p.x, p.y);
            *(float2*)&pb[(16 * t + q + 8) * PB_STRIDE + 2 * tig] = make_float2(p.z, p.w);
        }
        __syncwarp();

        // ---- owner epilogue: my reflection's 8 logits, contiguous ----
        float4 pa = *(float4*)&pb[lane * PB_STRIDE];
        float4 pc = *(float4*)&pb[lane * PB_STRIDE + 4];
        __syncwarp();   // reads done before next chunk's stores

        float pv[8] = {pa.x, pa.y, pa.z, pa.w, pc.x, pc.y, pc.z, pc.w};
        float fvv[8] = {f0.x, f0.y, f0.z, f0.w, f1.x, f1.y, f1.z, f1.w};

        float inv = 1.0f / sg_own;
        float si = 0.0f, ss = 0.0f;
#pragma unroll
        for (int c = 0; c < 8; c++) {
            float sc = softplus_f(pv[c]);
            float ip = fvv[c] * fvv[c] * sc;
            si += ip;
            float rr = (ip - io_own) * inv;
            ss = fmaf(rr, rr, ss);
        }

        // ONE coalesced store, ONE log, ONE seg_atomic
        __stcs(out + rown, si * 0.125f);
        float ll = fmaf(-0.5f, ss, -8.0f * (__logf(sg_own) + 0.5f * LOG_2PI_F));
        seg_atomic(ll, img_own, lane);
    }
}

// ---------------- kernel 3: parallel finalize (8 blocks, last writes scalars) ---
__global__ __launch_bounds__(1024) void finalize_kernel(float* __restrict__ out) {
    int i = blockIdx.x * 1024 + threadIdx.x;
    float v = g_img_sum[i] * (1.0f / fmaxf(g_img_cnt[i], 1.0f));
#pragma unroll
    for (int off = 16; off; off >>= 1)
        v += __shfl_down_sync(0xffffffffu, v, off);
    __shared__ float wsum[32];
    int lane = threadIdx.x & 31, wid = threadIdx.x >> 5;
    if (lane == 0) wsum[wid] = v;
    __syncthreads();
    if (wid == 0) {
        float t = wsum[lane];
#pragma unroll
        for (int off = 16; off; off >>= 1)
            t += __shfl_down_sync(0xffffffffu, t, off);
        if (lane == 0) {
            atomicAdd(&g_ll_total, t);
            __threadfence();
            unsigned ticket = atomicAdd(&g_done, 1u);
            if (ticket == gridDim.x - 1) {
                float total = atomicAdd(&g_ll_total, 0.0f);
                out[N_REFLNS]     = -(total / (float)MC) / (float)N_IMAGES;
                out[N_REFLNS + 1] = g_kl_sum * (1.0f / (float)N_RAC);
            }
        }
    }
}

// ---------------- launch ----------------
extern "C" void kernel_launch(void* const* d_in, const int* in_sizes, int n_in,
                              void* d_out, int out_size) {
    const float* q_loc     = (const float*)d_in[0];
    const float* q_ls      = (const float*)d_in[1];
    const float* eps       = (const float*)d_in[2];
    const float* metadata  = (const float*)d_in[3];
    const float* W1        = (const float*)d_in[4];
    const float* b1        = (const float*)d_in[5];
    const float* W2        = (const float*)d_in[6];
    const float* b2        = (const float*)d_in[7];
    const float* iobs      = (const float*)d_in[8];
    const float* sigiobs   = (const float*)d_in[9];
    const int*   image_id  = (const int*)d_in[10];
    const int*   miller_id = (const int*)d_in[11];
    float* out = (float*)d_out;

    zkl_kernel<<<(N_RAC + 255) / 256, 256>>>(q_loc, q_ls, eps);
    refl_kernel<<<2960, 128>>>(metadata, W1, b1, W2, b2,
                               iobs, sigiobs, image_id, miller_id, out);
    finalize_kernel<<<N_IMAGES / 1024, 1024>>>(out);
}